// round 1
// baseline (speedup 1.0000x reference)
#include <cuda_runtime.h>

// Problem constants (fixed by the dataset): B=256, F=32, N=32, D=256.
// Face and Ner both flatten to [8192, 256] row-major fp32.
#define NROWS 8192
#define KDIM  256
#define BATCH 256.0f

__device__ float g_valid[NROWS];

// Kernel 0: per-face-row validity flag (sum over D != 0) + zero the output scalar.
// One warp per row: 8192 rows / 8 warps per block = 1024 blocks.
__global__ void valid_kernel(const float* __restrict__ face, float* __restrict__ out) {
    int row  = blockIdx.x * 8 + (threadIdx.x >> 5);
    int lane = threadIdx.x & 31;
    const float* p = face + (size_t)row * KDIM;
    float s = 0.0f;
    #pragma unroll
    for (int i = lane; i < KDIM; i += 32) s += p[i];
    #pragma unroll
    for (int o = 16; o; o >>= 1) s += __shfl_xor_sync(0xffffffffu, s, o);
    if (lane == 0) g_valid[row] = (s != 0.0f) ? 1.0f : 0.0f;
    if (blockIdx.x == 0 && threadIdx.x == 0) out[0] = 0.0f;
}

// Kernel 1: fused GEMM-reduce.
// C[r][c] = dot(Face[r], Ner[c]); contribution:
//   diag (r>>5 == c>>5): relu(1 - C) ; else: relu(1 + C)
//   zero if C == 0 (padding rule), times valid[r]; global sum / 256.
#define BM 128
#define BN 128
#define BK 16

__global__ __launch_bounds__(256, 2)
void gemm_reduce_kernel(const float* __restrict__ A,   // face [8192,256]
                        const float* __restrict__ Bm,  // ner  [8192,256]
                        float* __restrict__ out) {
    __shared__ float As[BK][BM];
    __shared__ float Bs[BK][BN];
    __shared__ float red[8];

    const int tid = threadIdx.x;           // 256 threads
    const int tx  = tid & 15;              // 0..15 (cols)
    const int ty  = tid >> 4;              // 0..15 (rows)
    const int rowBase = blockIdx.y * BM;
    const int colBase = blockIdx.x * BN;

    float acc[8][8];
    #pragma unroll
    for (int i = 0; i < 8; i++)
        #pragma unroll
        for (int j = 0; j < 8; j++) acc[i][j] = 0.0f;

    // Global-load mapping: each thread loads 2 float4 (8 floats along K) of one row.
    const int lr = tid >> 1;          // 0..127: row within tile
    const int lk = (tid & 1) * 8;     // 0 or 8: K offset within BK chunk
    const float* Aptr = A  + (size_t)(rowBase + lr) * KDIM + lk;
    const float* Bptr = Bm + (size_t)(colBase + lr) * KDIM + lk;

    for (int k0 = 0; k0 < KDIM; k0 += BK) {
        float4 a0 = *(const float4*)(Aptr + k0);
        float4 a1 = *(const float4*)(Aptr + k0 + 4);
        float4 b0 = *(const float4*)(Bptr + k0);
        float4 b1 = *(const float4*)(Bptr + k0 + 4);

        __syncthreads();  // previous iter's smem reads complete
        As[lk + 0][lr] = a0.x; As[lk + 1][lr] = a0.y;
        As[lk + 2][lr] = a0.z; As[lk + 3][lr] = a0.w;
        As[lk + 4][lr] = a1.x; As[lk + 5][lr] = a1.y;
        As[lk + 6][lr] = a1.z; As[lk + 7][lr] = a1.w;
        Bs[lk + 0][lr] = b0.x; Bs[lk + 1][lr] = b0.y;
        Bs[lk + 2][lr] = b0.z; Bs[lk + 3][lr] = b0.w;
        Bs[lk + 4][lr] = b1.x; Bs[lk + 5][lr] = b1.y;
        Bs[lk + 6][lr] = b1.z; Bs[lk + 7][lr] = b1.w;
        __syncthreads();

        #pragma unroll
        for (int kk = 0; kk < BK; kk++) {
            float4 ra0 = *(const float4*)&As[kk][ty * 8];
            float4 ra1 = *(const float4*)&As[kk][ty * 8 + 4];
            float4 rb0 = *(const float4*)&Bs[kk][tx * 8];
            float4 rb1 = *(const float4*)&Bs[kk][tx * 8 + 4];
            float ar[8] = {ra0.x, ra0.y, ra0.z, ra0.w, ra1.x, ra1.y, ra1.z, ra1.w};
            float br[8] = {rb0.x, rb0.y, rb0.z, rb0.w, rb1.x, rb1.y, rb1.z, rb1.w};
            #pragma unroll
            for (int i = 0; i < 8; i++)
                #pragma unroll
                for (int j = 0; j < 8; j++)
                    acc[i][j] = fmaf(ar[i], br[j], acc[i][j]);
        }
    }

    // Epilogue: hinge + masks + local sum.
    float local = 0.0f;
    const int r0 = rowBase + ty * 8;
    const int c0 = colBase + tx * 8;
    #pragma unroll
    for (int i = 0; i < 8; i++) {
        const float v  = g_valid[r0 + i];
        const int   bi = (r0 + i) >> 5;  // batch index of this face row (F=32)
        #pragma unroll
        for (int j = 0; j < 8; j++) {
            const float c    = acc[i][j];
            const bool  diag = (bi == ((c0 + j) >> 5));  // k == b (N=32)
            float s = fmaxf(diag ? (1.0f - c) : (1.0f + c), 0.0f);
            if (c == 0.0f) s = 0.0f;  // sim==1 -> 0 rule (zero-dot padding)
            local += s * v;
        }
    }

    // Block reduction -> one atomicAdd per CTA.
    #pragma unroll
    for (int o = 16; o; o >>= 1) local += __shfl_xor_sync(0xffffffffu, local, o);
    if ((tid & 31) == 0) red[tid >> 5] = local;
    __syncthreads();
    if (tid < 8) {
        float s = red[tid];
        #pragma unroll
        for (int o = 4; o; o >>= 1) s += __shfl_xor_sync(0xffu, s, o, 8);
        if (tid == 0) atomicAdd(out, s * (1.0f / BATCH));
    }
}

extern "C" void kernel_launch(void* const* d_in, const int* in_sizes, int n_in,
                              void* d_out, int out_size) {
    const float* face = (const float*)d_in[0];  // [256,32,256] -> [8192,256]
    const float* ner  = (const float*)d_in[1];  // [256,32,256] -> [8192,256]
    float* out = (float*)d_out;

    valid_kernel<<<NROWS / 8, 256>>>(face, out);

    dim3 grid(NROWS / BN, NROWS / BM);  // 64 x 64
    gemm_reduce_kernel<<<grid, 256>>>(face, ner, out);
}

// round 5
// speedup vs baseline: 5.2198x; 5.2198x over previous
#include <cuda_runtime.h>
#include <cuda_bf16.h>
#include <cstdint>

// B=256, F=32, N=32, D=256 -> Face, Ner both [8192, 256] fp32 row-major.
#define NROWS 8192
#define KD    256

__device__ float g_valid[NROWS];
__device__ __align__(16) __nv_bfloat16 g_face16[NROWS * KD];
__device__ __align__(16) __nv_bfloat16 g_ner16 [NROWS * KD];

__device__ __forceinline__ uint32_t smem_u32(const void* p) {
    uint32_t a;
    asm("{ .reg .u64 t; cvta.to.shared.u64 t, %1; cvt.u32.u64 %0, t; }" : "=r"(a) : "l"(p));
    return a;
}
__device__ __forceinline__ void cp_async16(uint32_t s, const void* g) {
    asm volatile("cp.async.cg.shared.global [%0], [%1], 16;" :: "r"(s), "l"(g));
}
__device__ __forceinline__ void cp_commit() { asm volatile("cp.async.commit_group;"); }
__device__ __forceinline__ void cp_wait1()  { asm volatile("cp.async.wait_group 1;"); }
__device__ __forceinline__ void cp_wait0()  { asm volatile("cp.async.wait_group 0;"); }

__device__ __forceinline__ void ldsm_x4(uint32_t addr, uint32_t& r0, uint32_t& r1,
                                        uint32_t& r2, uint32_t& r3) {
    asm volatile("ldmatrix.sync.aligned.m8n8.x4.shared.b16 {%0,%1,%2,%3}, [%4];"
                 : "=r"(r0), "=r"(r1), "=r"(r2), "=r"(r3) : "r"(addr));
}
__device__ __forceinline__ void mma_16816(float* c, const uint32_t* a, const uint32_t* b) {
    asm volatile(
        "mma.sync.aligned.m16n8k16.row.col.f32.bf16.bf16.f32 "
        "{%0,%1,%2,%3}, {%4,%5,%6,%7}, {%8,%9}, {%0,%1,%2,%3};"
        : "+f"(c[0]), "+f"(c[1]), "+f"(c[2]), "+f"(c[3])
        : "r"(a[0]), "r"(a[1]), "r"(a[2]), "r"(a[3]), "r"(b[0]), "r"(b[1]));
}

// ───────── prep: fp32 -> bf16 + valid flags + zero out ─────────
__device__ __forceinline__ uint32_t pk(float x, float y) {
    __nv_bfloat162 t = __floats2bfloat162_rn(x, y);
    return *(uint32_t*)&t;
}
__global__ void prep_kernel(const float* __restrict__ face,
                            const float* __restrict__ ner,
                            float* __restrict__ out) {
    int row  = blockIdx.x * 8 + (threadIdx.x >> 5);
    int lane = threadIdx.x & 31;
    const float4* f = (const float4*)(face + (size_t)row * KD) + lane * 2;
    const float4* n = (const float4*)(ner  + (size_t)row * KD) + lane * 2;
    float4 a = f[0], b = f[1];
    float4 c = n[0], d = n[1];
    float s = a.x + a.y + a.z + a.w + b.x + b.y + b.z + b.w;
    #pragma unroll
    for (int o = 16; o; o >>= 1) s += __shfl_xor_sync(0xffffffffu, s, o);
    if (lane == 0) g_valid[row] = (s != 0.0f) ? 1.0f : 0.0f;
    uint4 fo = { pk(a.x, a.y), pk(a.z, a.w), pk(b.x, b.y), pk(b.z, b.w) };
    uint4 no = { pk(c.x, c.y), pk(c.z, c.w), pk(d.x, d.y), pk(d.z, d.w) };
    ((uint4*)(g_face16 + (size_t)row * KD))[lane] = fo;
    ((uint4*)(g_ner16  + (size_t)row * KD))[lane] = no;
    if (blockIdx.x == 0 && threadIdx.x == 0) out[0] = 0.0f;
}

// ───────── fused HMMA GEMM-reduce ─────────
// BM=128, BN=128, BK=32, 8 warps (4 m x 2 n), warp tile 32x64.
#define BK 32
#define SA 40   // padded row stride in bf16 (80 bytes): conflict-free ldmatrix

__global__ __launch_bounds__(256, 2)
void gemm_kernel(float* __restrict__ out) {
    __shared__ __nv_bfloat16 As[2][128 * SA];
    __shared__ __nv_bfloat16 Bs[2][128 * SA];
    __shared__ float v_s[128];
    __shared__ float red[8];

    const int tid  = threadIdx.x;
    const int wid  = tid >> 5;
    const int lane = tid & 31;
    const int wm   = wid >> 1;          // 0..3 (m)
    const int wn   = wid & 1;           // 0..1 (n)
    const int rowBase = blockIdx.y * 128;
    const int colBase = blockIdx.x * 128;

    // valid cache for this CTA's 128 face rows
    if (tid < 128) v_s[tid] = g_valid[rowBase + tid];

    const uint32_t aS = smem_u32(As);
    const uint32_t bS = smem_u32(Bs);

    auto load_stage = [&](int stage, int k0) {
        uint32_t as = aS + stage * 128 * SA * 2;
        uint32_t bs = bS + stage * 128 * SA * 2;
        #pragma unroll
        for (int h = 0; h < 2; h++) {
            int id  = tid + h * 256;
            int r   = id >> 2, c = id & 3;
            uint32_t so = r * (SA * 2) + c * 16;
            const __nv_bfloat16* ga = g_face16 + (size_t)(rowBase + r) * KD + k0 + c * 8;
            const __nv_bfloat16* gb = g_ner16  + (size_t)(colBase + r) * KD + k0 + c * 8;
            cp_async16(as + so, ga);
            cp_async16(bs + so, gb);
        }
    };

    float acc[2][8][4];
    #pragma unroll
    for (int i = 0; i < 2; i++)
        #pragma unroll
        for (int j = 0; j < 8; j++)
            #pragma unroll
            for (int k = 0; k < 4; k++) acc[i][j][k] = 0.0f;

    load_stage(0, 0);
    cp_commit();

    // ldmatrix source addresses (within a stage), per warp:
    // A: row = wm*32 + mi*16 + (lane&15), col = ks*16 + (lane>>4)*8
    // B: row = wn*64 + nt*16 + (lane&7) + ((lane>>4)<<3), col = ks*16 + ((lane>>3)&1)*8
    const int arow = wm * 32 + (lane & 15);
    const int acol = (lane >> 4) * 8;
    const int brow = wn * 64 + (lane & 7) + ((lane >> 4) << 3);
    const int bcol = ((lane >> 3) & 1) * 8;

    #pragma unroll 1
    for (int it = 0; it < KD / BK; it++) {
        if (it < KD / BK - 1) { load_stage((it + 1) & 1, (it + 1) * BK); cp_commit(); cp_wait1(); }
        else cp_wait0();
        __syncthreads();

        const int st = it & 1;
        const uint32_t aBase = aS + st * 128 * SA * 2;
        const uint32_t bBase = bS + st * 128 * SA * 2;

        #pragma unroll
        for (int ks = 0; ks < 2; ks++) {
            uint32_t a[2][4];
            #pragma unroll
            for (int mi = 0; mi < 2; mi++) {
                uint32_t ad = aBase + (arow + mi * 16) * (SA * 2) + (ks * 16 + acol) * 2;
                ldsm_x4(ad, a[mi][0], a[mi][1], a[mi][2], a[mi][3]);
            }
            uint32_t b[8][2];
            #pragma unroll
            for (int nt = 0; nt < 4; nt++) {
                uint32_t r0, r1, r2, r3;
                uint32_t bd = bBase + (brow + nt * 16) * (SA * 2) + (ks * 16 + bcol) * 2;
                ldsm_x4(bd, r0, r1, r2, r3);
                b[nt * 2 + 0][0] = r0; b[nt * 2 + 0][1] = r1;
                b[nt * 2 + 1][0] = r2; b[nt * 2 + 1][1] = r3;
            }
            #pragma unroll
            for (int mi = 0; mi < 2; mi++)
                #pragma unroll
                for (int nj = 0; nj < 8; nj++)
                    mma_16816(acc[mi][nj], a[mi], b[nj]);
        }
        __syncthreads();
    }

    // ── epilogue: hinge + valid mask + sum ──
    // acc[mi][nj][k]: row = wm*32 + mi*16 + (lane>>2) + (k>=2 ? 8 : 0)
    //                 col = colBase + wn*64 + nj*8 + (lane&3)*2 + (k&1)
    const bool diagCTA = (blockIdx.x == blockIdx.y);
    float local = 0.0f;
    #pragma unroll
    for (int mi = 0; mi < 2; mi++) {
        #pragma unroll
        for (int half = 0; half < 2; half++) {   // k<2 vs k>=2 (row, row+8)
            const int rloc = wm * 32 + mi * 16 + (lane >> 2) + half * 8;
            const float v  = v_s[rloc];
            const int  bi  = (rowBase + rloc) >> 5;
            float rs = 0.0f;
            #pragma unroll
            for (int nj = 0; nj < 8; nj++) {
                #pragma unroll
                for (int q = 0; q < 2; q++) {
                    const float c = acc[mi][nj][half * 2 + q];
                    float sign = 1.0f;
                    if (diagCTA) {
                        const int col = colBase + wn * 64 + nj * 8 + (lane & 3) * 2 + q;
                        sign = (bi == (col >> 5)) ? -1.0f : 1.0f;
                    }
                    float s = fmaxf(fmaf(sign, c, 1.0f), 0.0f);
                    if (c == 0.0f) s = 0.0f;   // sim==1 -> 0 (zero-dot padding rule)
                    rs += s;
                }
            }
            local += rs * v;
        }
    }

    #pragma unroll
    for (int o = 16; o; o >>= 1) local += __shfl_xor_sync(0xffffffffu, local, o);
    if (lane == 0) red[wid] = local;
    __syncthreads();
    if (tid == 0) {
        float s = 0.0f;
        #pragma unroll
        for (int i = 0; i < 8; i++) s += red[i];
        atomicAdd(out, s * (1.0f / 256.0f));
    }
}

extern "C" void kernel_launch(void* const* d_in, const int* in_sizes, int n_in,
                              void* d_out, int out_size) {
    const float* face = (const float*)d_in[0];
    const float* ner  = (const float*)d_in[1];
    float* out = (float*)d_out;

    prep_kernel<<<NROWS / 8, 256>>>(face, ner, out);
    dim3 grid(64, 64);
    gemm_kernel<<<grid, 256>>>(out);
}

// round 7
// speedup vs baseline: 5.3521x; 1.0254x over previous
#include <cuda_runtime.h>
#include <cuda_bf16.h>
#include <cstdint>

// B=256, F=32, N=32, D=256 -> Face, Ner both [8192, 256] fp32 row-major.
#define NROWS 8192
#define KD    256

__device__ float g_valid[NROWS];
__device__ __align__(16) __nv_bfloat16 g_face16[NROWS * KD];
__device__ __align__(16) __nv_bfloat16 g_ner16 [NROWS * KD];

__device__ __forceinline__ uint32_t smem_u32(const void* p) {
    uint32_t a;
    asm("{ .reg .u64 t; cvta.to.shared.u64 t, %1; cvt.u32.u64 %0, t; }" : "=r"(a) : "l"(p));
    return a;
}
__device__ __forceinline__ void cp_async16(uint32_t s, const void* g) {
    asm volatile("cp.async.cg.shared.global [%0], [%1], 16;" :: "r"(s), "l"(g));
}
__device__ __forceinline__ void cp_commit() { asm volatile("cp.async.commit_group;"); }

__device__ __forceinline__ void ldsm_x4(uint32_t addr, uint32_t& r0, uint32_t& r1,
                                        uint32_t& r2, uint32_t& r3) {
    asm volatile("ldmatrix.sync.aligned.m8n8.x4.shared.b16 {%0,%1,%2,%3}, [%4];"
                 : "=r"(r0), "=r"(r1), "=r"(r2), "=r"(r3) : "r"(addr));
}
__device__ __forceinline__ void mma_16816(float* c, const uint32_t* a, const uint32_t* b) {
    asm volatile(
        "mma.sync.aligned.m16n8k16.row.col.f32.bf16.bf16.f32 "
        "{%0,%1,%2,%3}, {%4,%5,%6,%7}, {%8,%9}, {%0,%1,%2,%3};"
        : "+f"(c[0]), "+f"(c[1]), "+f"(c[2]), "+f"(c[3])
        : "r"(a[0]), "r"(a[1]), "r"(a[2]), "r"(a[3]), "r"(b[0]), "r"(b[1]));
}

// ───────── prep: fp32 -> bf16 + valid flags + zero out ─────────
__device__ __forceinline__ uint32_t pk(float x, float y) {
    __nv_bfloat162 t = __floats2bfloat162_rn(x, y);
    return *(uint32_t*)&t;
}
__global__ void prep_kernel(const float* __restrict__ face,
                            const float* __restrict__ ner,
                            float* __restrict__ out) {
    int row  = blockIdx.x * 8 + (threadIdx.x >> 5);
    int lane = threadIdx.x & 31;
    const float4* f = (const float4*)(face + (size_t)row * KD) + lane * 2;
    const float4* n = (const float4*)(ner  + (size_t)row * KD) + lane * 2;
    float4 a = f[0], b = f[1];
    float4 c = n[0], d = n[1];
    float s = a.x + a.y + a.z + a.w + b.x + b.y + b.z + b.w;
    #pragma unroll
    for (int o = 16; o; o >>= 1) s += __shfl_xor_sync(0xffffffffu, s, o);
    if (lane == 0) g_valid[row] = (s != 0.0f) ? 1.0f : 0.0f;
    uint4 fo = { pk(a.x, a.y), pk(a.z, a.w), pk(b.x, b.y), pk(b.z, b.w) };
    uint4 no = { pk(c.x, c.y), pk(c.z, c.w), pk(d.x, d.y), pk(d.z, d.w) };
    ((uint4*)(g_face16 + (size_t)row * KD))[lane] = fo;
    ((uint4*)(g_ner16  + (size_t)row * KD))[lane] = no;
    if (blockIdx.x == 0 && threadIdx.x == 0) out[0] = 0.0f;
}

// ───────── fused HMMA GEMM-reduce ─────────
// BM=128, BN=128, BK=32, 3-stage cp.async pipeline, 8 warps (4m x 2n), warp tile 32x64.
#define BK   32
#define SA   40                    // padded row stride in bf16 (80 B)
#define STG  (128 * SA * 2)        // 10240 B per matrix per stage
#define BOFF (3 * STG)             // B stages start after 3 A stages
#define VOFF (6 * STG)             // v_s
#define ROFF (VOFF + 512)          // red
#define SMEM_BYTES (ROFF + 64)

__global__ __launch_bounds__(256, 2)
void gemm_kernel(float* __restrict__ out) {
    extern __shared__ char dsmem[];
    const uint32_t sb = smem_u32(dsmem);
    float* v_s = (float*)(dsmem + VOFF);
    float* red = (float*)(dsmem + ROFF);

    const int tid  = threadIdx.x;
    const int wid  = tid >> 5;
    const int lane = tid & 31;
    const int wm   = wid >> 1;          // 0..3 (m)
    const int wn   = wid & 1;           // 0..1 (n)
    const int rowBase = blockIdx.y * 128;
    const int colBase = blockIdx.x * 128;

    if (tid < 128) v_s[tid] = g_valid[rowBase + tid];

    // ── loader: each thread owns 2 16B chunks per matrix per stage (hoisted) ──
    const int r0  = tid >> 2;                 // 0..63
    const int c0  = tid & 3;                  // 0..3
    const uint32_t so0 = r0 * (SA * 2) + c0 * 16;
    const uint32_t so1 = so0 + 64 * (SA * 2);
    const __nv_bfloat16* gA0 = g_face16 + (size_t)(rowBase + r0) * KD + c0 * 8;
    const __nv_bfloat16* gA1 = gA0 + (size_t)64 * KD;
    const __nv_bfloat16* gB0 = g_ner16  + (size_t)(colBase + r0) * KD + c0 * 8;
    const __nv_bfloat16* gB1 = gB0 + (size_t)64 * KD;

    auto load_stage = [&](int stage, int k0) {
        const uint32_t as = sb + stage * STG;
        const uint32_t bs = sb + BOFF + stage * STG;
        cp_async16(as + so0, gA0 + k0);
        cp_async16(as + so1, gA1 + k0);
        cp_async16(bs + so0, gB0 + k0);
        cp_async16(bs + so1, gB1 + k0);
    };

    float acc[2][8][4];
    #pragma unroll
    for (int i = 0; i < 2; i++)
        #pragma unroll
        for (int j = 0; j < 8; j++)
            #pragma unroll
            for (int k = 0; k < 4; k++) acc[i][j][k] = 0.0f;

    load_stage(0, 0);  cp_commit();
    load_stage(1, BK); cp_commit();

    // ── hoisted ldmatrix offsets (bytes within a stage) ──
    // A: row = wm*32 + mi*16 + (lane&15), col8 = (lane>>4)
    // B: row = wn*64 + nt*16 + (lane&7) + ((lane>>4)<<3), col8 = ((lane>>3)&1)
    const uint32_t aOff0 = (wm * 32 + (lane & 15)) * (SA * 2) + ((lane >> 4) * 8) * 2;
    const uint32_t aOff1 = aOff0 + 16 * (SA * 2);
    const uint32_t bOffB = (wn * 64 + (lane & 7) + ((lane >> 4) << 3)) * (SA * 2)
                         + (((lane >> 3) & 1) * 8) * 2;

    #pragma unroll 1
    for (int it = 0; it < KD / BK; it++) {
        asm volatile("cp.async.wait_group 1;" ::: "memory");
        __syncthreads();
        if (it + 2 < KD / BK) load_stage((it + 2) % 3, (it + 2) * BK);
        cp_commit();   // empty group in tail iterations keeps the count invariant

        const int st = it % 3;
        const uint32_t aBase = sb + st * STG;
        const uint32_t bBase = sb + BOFF + st * STG;

        #pragma unroll
        for (int ks = 0; ks < 2; ks++) {
            const uint32_t kAdd = ks * 32;   // 16 bf16 = 32 B
            uint32_t a[2][4];
            ldsm_x4(aBase + aOff0 + kAdd, a[0][0], a[0][1], a[0][2], a[0][3]);
            ldsm_x4(aBase + aOff1 + kAdd, a[1][0], a[1][1], a[1][2], a[1][3]);
            uint32_t b[8][2];
            #pragma unroll
            for (int nt = 0; nt < 4; nt++) {
                uint32_t q0, q1, q2, q3;
                ldsm_x4(bBase + bOffB + nt * (16 * SA * 2) + kAdd, q0, q1, q2, q3);
                b[nt * 2 + 0][0] = q0; b[nt * 2 + 0][1] = q1;
                b[nt * 2 + 1][0] = q2; b[nt * 2 + 1][1] = q3;
            }
            #pragma unroll
            for (int mi = 0; mi < 2; mi++)
                #pragma unroll
                for (int nj = 0; nj < 8; nj++)
                    mma_16816(acc[mi][nj], a[mi], b[nj]);
        }
    }

    // ── epilogue: hinge + valid mask + sum ──
    // acc[mi][nj][k]: row = wm*32 + mi*16 + (lane>>2) + (k>=2 ? 8 : 0)
    //                 col = colBase + wn*64 + nj*8 + (lane&3)*2 + (k&1)
    const bool diagCTA = (blockIdx.x == blockIdx.y);
    float local = 0.0f;
    #pragma unroll
    for (int mi = 0; mi < 2; mi++) {
        #pragma unroll
        for (int half = 0; half < 2; half++) {
            const int rloc = wm * 32 + mi * 16 + (lane >> 2) + half * 8;
            const float v  = v_s[rloc];
            const int  bi  = (rowBase + rloc) >> 5;
            float rs = 0.0f;
            #pragma unroll
            for (int nj = 0; nj < 8; nj++) {
                #pragma unroll
                for (int q = 0; q < 2; q++) {
                    const float c = acc[mi][nj][half * 2 + q];
                    float sign = 1.0f;
                    if (diagCTA) {
                        const int col = colBase + wn * 64 + nj * 8 + (lane & 3) * 2 + q;
                        sign = (bi == (col >> 5)) ? -1.0f : 1.0f;
                    }
                    float s = fmaxf(fmaf(sign, c, 1.0f), 0.0f);
                    if (c == 0.0f) s = 0.0f;   // sim==1 -> 0 (zero-dot padding rule)
                    rs += s;
                }
            }
            local += rs * v;
        }
    }

    #pragma unroll
    for (int o = 16; o; o >>= 1) local += __shfl_xor_sync(0xffffffffu, local, o);
    if (lane == 0) red[wid] = local;
    __syncthreads();
    if (tid == 0) {
        float s = 0.0f;
        #pragma unroll
        for (int i = 0; i < 8; i++) s += red[i];
        atomicAdd(out, s * (1.0f / 256.0f));
    }
}

extern "C" void kernel_launch(void* const* d_in, const int* in_sizes, int n_in,
                              void* d_out, int out_size) {
    const float* face = (const float*)d_in[0];
    const float* ner  = (const float*)d_in[1];
    float* out = (float*)d_out;

    cudaFuncSetAttribute(gemm_kernel, cudaFuncAttributeMaxDynamicSharedMemorySize, SMEM_BYTES);

    prep_kernel<<<NROWS / 8, 256>>>(face, ner, out);
    dim3 grid(64, 64);
    gemm_kernel<<<grid, 256, SMEM_BYTES>>>(out);
}